// round 1
// baseline (speedup 1.0000x reference)
#include <cuda_runtime.h>
#include <cuda_bf16.h>
#include <stdint.h>

#define SEQS 4096
#define TT   64
#define CC   64
#define NH   8
#define HS   8
#define FF   256

// Dynamic smem layout (bytes):
//  [0,16384)          float  xf[64][64]    residual stream (x, then x+attn_proj)
//  [16384,25600)      bf16   hb[64][72]    LN output (h, then h2)
//  [25600,34816)      bf16   attnb[64][72] concat attention output
//  [34816,68608)      bf16   scr[64][264]  qkv (cols 0..191) then fc1 act (cols 0..255)
#define SMEM_BYTES 68608

// bf16 transposed weights (prepared once per launch)
__device__ __align__(16) __nv_bfloat16 g_wqkvT[192 * 64];   // [n=3C][k=C]  n: 0..63 q, 64..127 k, 128..191 v (head-major)
__device__ __align__(16) __nv_bfloat16 g_projT[64 * 64];    // [n][k]
__device__ __align__(16) __nv_bfloat16 g_fc1T[256 * 64];    // [n][k]
__device__ __align__(16) __nv_bfloat16 g_fc2T[64 * 256];    // [n][k]

__global__ void prep_kernel(const float* __restrict__ wq, const float* __restrict__ wk,
                            const float* __restrict__ wv, const float* __restrict__ projw,
                            const float* __restrict__ fc1w, const float* __restrict__ fc2w) {
    int stride = gridDim.x * blockDim.x;
    int t0 = blockIdx.x * blockDim.x + threadIdx.x;
    for (int idx = t0; idx < 192 * 64; idx += stride) {
        int n = idx >> 6, k = idx & 63;
        float v;
        if (n < 64)            v = wq[(((n      ) >> 3) * 64 + k) * 8 + ( n        & 7)];
        else if (n < 128)      v = wk[(((n -  64) >> 3) * 64 + k) * 8 + ((n -  64) & 7)];
        else                   v = wv[(((n - 128) >> 3) * 64 + k) * 8 + ((n - 128) & 7)];
        g_wqkvT[idx] = __float2bfloat16(v);
    }
    for (int idx = t0; idx < 64 * 64; idx += stride) {
        int n = idx >> 6, k = idx & 63;
        g_projT[idx] = __float2bfloat16(projw[k * 64 + n]);
    }
    for (int idx = t0; idx < 256 * 64; idx += stride) {
        int n = idx >> 6, k = idx & 63;
        g_fc1T[idx] = __float2bfloat16(fc1w[k * 256 + n]);
    }
    for (int idx = t0; idx < 64 * 256; idx += stride) {
        int n = idx >> 8, k = idx & 255;
        g_fc2T[idx] = __float2bfloat16(fc2w[k * 64 + n]);
    }
}

__device__ __forceinline__ void mma16816(float* c, const uint32_t* a, const uint32_t* b) {
    asm volatile(
        "mma.sync.aligned.m16n8k16.row.col.f32.bf16.bf16.f32 "
        "{%0,%1,%2,%3}, {%4,%5,%6,%7}, {%8,%9}, {%0,%1,%2,%3};\n"
        : "+f"(c[0]), "+f"(c[1]), "+f"(c[2]), "+f"(c[3])
        : "r"(a[0]), "r"(a[1]), "r"(a[2]), "r"(a[3]), "r"(b[0]), "r"(b[1]));
}

__device__ __forceinline__ void mma1688(float* c, const uint32_t* a, uint32_t b) {
    asm volatile(
        "mma.sync.aligned.m16n8k8.row.col.f32.bf16.bf16.f32 "
        "{%0,%1,%2,%3}, {%4,%5}, {%6}, {%0,%1,%2,%3};\n"
        : "+f"(c[0]), "+f"(c[1]), "+f"(c[2]), "+f"(c[3])
        : "r"(a[0]), "r"(a[1]), "r"(b));
}

__device__ __forceinline__ uint32_t packbf(float lo, float hi) {
    __nv_bfloat162 t = __floats2bfloat162_rn(lo, hi);
    return *reinterpret_cast<uint32_t*>(&t);
}

__global__ __launch_bounds__(128) void block_kernel(
    const float* __restrict__ x,
    const float* __restrict__ ln1w, const float* __restrict__ ln1b,
    const float* __restrict__ projb,
    const float* __restrict__ ln2w, const float* __restrict__ ln2b,
    const float* __restrict__ fc1b, const float* __restrict__ fc2b,
    float* __restrict__ out)
{
    extern __shared__ char smraw[];
    float* xf = reinterpret_cast<float*>(smraw);
    __nv_bfloat16* hb    = reinterpret_cast<__nv_bfloat16*>(smraw + 16384);
    __nv_bfloat16* attnb = reinterpret_cast<__nv_bfloat16*>(smraw + 25600);
    __nv_bfloat16* scr   = reinterpret_cast<__nv_bfloat16*>(smraw + 34816);

    const int tid  = threadIdx.x;
    const int w    = tid >> 5;
    const int lane = tid & 31;
    const int g    = lane >> 2;   // group id (row within tile / n col)
    const int qd   = lane & 3;    // thread-in-group
    const int s    = blockIdx.x;  // sequence
    const int m0   = w * 16;      // this warp's row tile

    // ---- load x tile [64][64] fp32 ----
    {
        const float4* xg = reinterpret_cast<const float4*>(x + (size_t)s * TT * CC);
        float4* xs = reinterpret_cast<float4*>(xf);
#pragma unroll
        for (int i = 0; i < 8; ++i) xs[tid + i * 128] = xg[tid + i * 128];
    }
    __syncthreads();

    // ---- LN1 on this warp's 16 rows -> hb (bf16) ----
    {
        float w0 = ln1w[lane], w1 = ln1w[lane + 32];
        float b0 = ln1b[lane], b1 = ln1b[lane + 32];
        for (int r = m0; r < m0 + 16; ++r) {
            float v0 = xf[r * 64 + lane], v1 = xf[r * 64 + lane + 32];
            float sum = v0 + v1, sq = v0 * v0 + v1 * v1;
#pragma unroll
            for (int o = 16; o; o >>= 1) {
                sum += __shfl_xor_sync(0xffffffffu, sum, o);
                sq  += __shfl_xor_sync(0xffffffffu, sq, o);
            }
            float mu = sum * 0.015625f;
            float rs = rsqrtf(sq * 0.015625f - mu * mu + 1e-5f);
            hb[r * 72 + lane]      = __float2bfloat16((v0 - mu) * rs * w0 + b0);
            hb[r * 72 + lane + 32] = __float2bfloat16((v1 - mu) * rs * w1 + b1);
        }
    }
    __syncwarp();

    // ---- QKV: D[64][192] = h @ Wqkv, rows m0..m0+15 per warp -> scr ----
    {
        uint32_t a[4][4];
#pragma unroll
        for (int kk = 0; kk < 4; ++kk) {
            int k0 = kk * 16;
            a[kk][0] = *reinterpret_cast<const uint32_t*>(&hb[(m0 + g)     * 72 + k0 + 2 * qd]);
            a[kk][1] = *reinterpret_cast<const uint32_t*>(&hb[(m0 + g + 8) * 72 + k0 + 2 * qd]);
            a[kk][2] = *reinterpret_cast<const uint32_t*>(&hb[(m0 + g)     * 72 + k0 + 2 * qd + 8]);
            a[kk][3] = *reinterpret_cast<const uint32_t*>(&hb[(m0 + g + 8) * 72 + k0 + 2 * qd + 8]);
        }
        for (int n0 = 0; n0 < 192; n0 += 8) {
            float c[4] = {0.f, 0.f, 0.f, 0.f};
#pragma unroll
            for (int kk = 0; kk < 4; ++kk) {
                uint32_t b[2];
                b[0] = *reinterpret_cast<const uint32_t*>(&g_wqkvT[(n0 + g) * 64 + kk * 16 + 2 * qd]);
                b[1] = *reinterpret_cast<const uint32_t*>(&g_wqkvT[(n0 + g) * 64 + kk * 16 + 2 * qd + 8]);
                mma16816(c, a[kk], b);
            }
            *reinterpret_cast<uint32_t*>(&scr[(m0 + g)     * 264 + n0 + 2 * qd]) = packbf(c[0], c[1]);
            *reinterpret_cast<uint32_t*>(&scr[(m0 + g + 8) * 264 + n0 + 2 * qd]) = packbf(c[2], c[3]);
        }
    }
    __syncthreads();

    // ---- attention: warp w handles heads 2w, 2w+1, all 64 rows ----
#pragma unroll
    for (int hh = 0; hh < 2; ++hh) {
        const int hd = w * 2 + hh;
        const int qcol = hd * 8, kcol = 64 + hd * 8, vcol = 128 + hd * 8;
#pragma unroll
        for (int mt = 0; mt < 4; ++mt) {
            const int t0 = mt * 16;
            const int ntm = 2 * mt + 1;   // last n-tile (causal)
            uint32_t aq[2];
            aq[0] = *reinterpret_cast<const uint32_t*>(&scr[(t0 + g)     * 264 + qcol + 2 * qd]);
            aq[1] = *reinterpret_cast<const uint32_t*>(&scr[(t0 + g + 8) * 264 + qcol + 2 * qd]);
            float sc[8][4];
#pragma unroll
            for (int nt = 0; nt < 8; ++nt) {
                if (nt > ntm) continue;
                sc[nt][0] = sc[nt][1] = sc[nt][2] = sc[nt][3] = 0.f;
                uint32_t bk = *reinterpret_cast<const uint32_t*>(&scr[(nt * 8 + g) * 264 + kcol + 2 * qd]);
                mma1688(sc[nt], aq, bk);
            }
            const int rlo = t0 + g, rhi = t0 + g + 8;
            float mlo = -1e30f, mhi = -1e30f;
#pragma unroll
            for (int nt = 0; nt < 8; ++nt) {
                if (nt > ntm) continue;
#pragma unroll
                for (int e = 0; e < 2; ++e) {
                    int col = nt * 8 + 2 * qd + e;
                    float v0 = sc[nt][e] * 0.125f;     if (col > rlo) v0 = -1e30f;
                    float v1 = sc[nt][2 + e] * 0.125f; if (col > rhi) v1 = -1e30f;
                    sc[nt][e] = v0; sc[nt][2 + e] = v1;
                    mlo = fmaxf(mlo, v0); mhi = fmaxf(mhi, v1);
                }
            }
            mlo = fmaxf(mlo, __shfl_xor_sync(0xffffffffu, mlo, 1));
            mlo = fmaxf(mlo, __shfl_xor_sync(0xffffffffu, mlo, 2));
            mhi = fmaxf(mhi, __shfl_xor_sync(0xffffffffu, mhi, 1));
            mhi = fmaxf(mhi, __shfl_xor_sync(0xffffffffu, mhi, 2));
            float slo = 0.f, shi = 0.f;
#pragma unroll
            for (int nt = 0; nt < 8; ++nt) {
                if (nt > ntm) continue;
#pragma unroll
                for (int e = 0; e < 2; ++e) {
                    float p0 = __expf(sc[nt][e] - mlo);
                    float p1 = __expf(sc[nt][2 + e] - mhi);
                    sc[nt][e] = p0; sc[nt][2 + e] = p1;
                    slo += p0; shi += p1;
                }
            }
            slo += __shfl_xor_sync(0xffffffffu, slo, 1);
            slo += __shfl_xor_sync(0xffffffffu, slo, 2);
            shi += __shfl_xor_sync(0xffffffffu, shi, 1);
            shi += __shfl_xor_sync(0xffffffffu, shi, 2);
            // P @ V
            float acc[4] = {0.f, 0.f, 0.f, 0.f};
#pragma unroll
            for (int kc = 0; kc < 4; ++kc) {
                if (kc > mt) continue;
                uint32_t pa[4];
                pa[0] = packbf(sc[2 * kc][0],     sc[2 * kc][1]);
                pa[1] = packbf(sc[2 * kc][2],     sc[2 * kc][3]);
                pa[2] = packbf(sc[2 * kc + 1][0], sc[2 * kc + 1][1]);
                pa[3] = packbf(sc[2 * kc + 1][2], sc[2 * kc + 1][3]);
                const int sb = kc * 16;
                uint16_t v00 = *reinterpret_cast<const uint16_t*>(&scr[(sb + 2 * qd)     * 264 + vcol + g]);
                uint16_t v01 = *reinterpret_cast<const uint16_t*>(&scr[(sb + 2 * qd + 1) * 264 + vcol + g]);
                uint16_t v10 = *reinterpret_cast<const uint16_t*>(&scr[(sb + 2 * qd + 8) * 264 + vcol + g]);
                uint16_t v11 = *reinterpret_cast<const uint16_t*>(&scr[(sb + 2 * qd + 9) * 264 + vcol + g]);
                uint32_t b[2];
                b[0] = (uint32_t)v00 | ((uint32_t)v01 << 16);
                b[1] = (uint32_t)v10 | ((uint32_t)v11 << 16);
                mma16816(acc, pa, b);
            }
            float ilo = 1.f / slo, ihi = 1.f / shi;
            *reinterpret_cast<uint32_t*>(&attnb[(t0 + g)     * 72 + qcol + 2 * qd]) = packbf(acc[0] * ilo, acc[1] * ilo);
            *reinterpret_cast<uint32_t*>(&attnb[(t0 + g + 8) * 72 + qcol + 2 * qd]) = packbf(acc[2] * ihi, acc[3] * ihi);
        }
    }
    __syncthreads();

    // ---- proj + residual into xf (fp32) ----
    {
        uint32_t a[4][4];
#pragma unroll
        for (int kk = 0; kk < 4; ++kk) {
            int k0 = kk * 16;
            a[kk][0] = *reinterpret_cast<const uint32_t*>(&attnb[(m0 + g)     * 72 + k0 + 2 * qd]);
            a[kk][1] = *reinterpret_cast<const uint32_t*>(&attnb[(m0 + g + 8) * 72 + k0 + 2 * qd]);
            a[kk][2] = *reinterpret_cast<const uint32_t*>(&attnb[(m0 + g)     * 72 + k0 + 2 * qd + 8]);
            a[kk][3] = *reinterpret_cast<const uint32_t*>(&attnb[(m0 + g + 8) * 72 + k0 + 2 * qd + 8]);
        }
#pragma unroll
        for (int n0 = 0; n0 < 64; n0 += 8) {
            float c[4] = {0.f, 0.f, 0.f, 0.f};
#pragma unroll
            for (int kk = 0; kk < 4; ++kk) {
                uint32_t b[2];
                b[0] = *reinterpret_cast<const uint32_t*>(&g_projT[(n0 + g) * 64 + kk * 16 + 2 * qd]);
                b[1] = *reinterpret_cast<const uint32_t*>(&g_projT[(n0 + g) * 64 + kk * 16 + 2 * qd + 8]);
                mma16816(c, a[kk], b);
            }
            int c0 = n0 + 2 * qd;
            float pb0 = projb[c0], pb1 = projb[c0 + 1];
            xf[(m0 + g)     * 64 + c0]     += c[0] + pb0;
            xf[(m0 + g)     * 64 + c0 + 1] += c[1] + pb1;
            xf[(m0 + g + 8) * 64 + c0]     += c[2] + pb0;
            xf[(m0 + g + 8) * 64 + c0 + 1] += c[3] + pb1;
        }
    }
    __syncwarp();

    // ---- LN2 -> hb ----
    {
        float w0 = ln2w[lane], w1 = ln2w[lane + 32];
        float b0 = ln2b[lane], b1 = ln2b[lane + 32];
        for (int r = m0; r < m0 + 16; ++r) {
            float v0 = xf[r * 64 + lane], v1 = xf[r * 64 + lane + 32];
            float sum = v0 + v1, sq = v0 * v0 + v1 * v1;
#pragma unroll
            for (int o = 16; o; o >>= 1) {
                sum += __shfl_xor_sync(0xffffffffu, sum, o);
                sq  += __shfl_xor_sync(0xffffffffu, sq, o);
            }
            float mu = sum * 0.015625f;
            float rs = rsqrtf(sq * 0.015625f - mu * mu + 1e-5f);
            hb[r * 72 + lane]      = __float2bfloat16((v0 - mu) * rs * w0 + b0);
            hb[r * 72 + lane + 32] = __float2bfloat16((v1 - mu) * rs * w1 + b1);
        }
    }
    __syncwarp();

    // ---- fc1 + relu -> scr (bf16 [64][256]) ----
    {
        uint32_t a[4][4];
#pragma unroll
        for (int kk = 0; kk < 4; ++kk) {
            int k0 = kk * 16;
            a[kk][0] = *reinterpret_cast<const uint32_t*>(&hb[(m0 + g)     * 72 + k0 + 2 * qd]);
            a[kk][1] = *reinterpret_cast<const uint32_t*>(&hb[(m0 + g + 8) * 72 + k0 + 2 * qd]);
            a[kk][2] = *reinterpret_cast<const uint32_t*>(&hb[(m0 + g)     * 72 + k0 + 2 * qd + 8]);
            a[kk][3] = *reinterpret_cast<const uint32_t*>(&hb[(m0 + g + 8) * 72 + k0 + 2 * qd + 8]);
        }
        for (int n0 = 0; n0 < 256; n0 += 8) {
            float c[4] = {0.f, 0.f, 0.f, 0.f};
#pragma unroll
            for (int kk = 0; kk < 4; ++kk) {
                uint32_t b[2];
                b[0] = *reinterpret_cast<const uint32_t*>(&g_fc1T[(n0 + g) * 64 + kk * 16 + 2 * qd]);
                b[1] = *reinterpret_cast<const uint32_t*>(&g_fc1T[(n0 + g) * 64 + kk * 16 + 2 * qd + 8]);
                mma16816(c, a[kk], b);
            }
            int c0 = n0 + 2 * qd;
            float f0 = fc1b[c0], f1 = fc1b[c0 + 1];
            *reinterpret_cast<uint32_t*>(&scr[(m0 + g)     * 264 + c0]) =
                packbf(fmaxf(c[0] + f0, 0.f), fmaxf(c[1] + f1, 0.f));
            *reinterpret_cast<uint32_t*>(&scr[(m0 + g + 8) * 264 + c0]) =
                packbf(fmaxf(c[2] + f0, 0.f), fmaxf(c[3] + f1, 0.f));
        }
    }
    __syncwarp();

    // ---- fc2 + residual -> out (fp32) ----
    {
#pragma unroll
        for (int n0 = 0; n0 < 64; n0 += 8) {
            float c[4] = {0.f, 0.f, 0.f, 0.f};
#pragma unroll
            for (int kk = 0; kk < 16; ++kk) {
                uint32_t a[4];
                a[0] = *reinterpret_cast<const uint32_t*>(&scr[(m0 + g)     * 264 + kk * 16 + 2 * qd]);
                a[1] = *reinterpret_cast<const uint32_t*>(&scr[(m0 + g + 8) * 264 + kk * 16 + 2 * qd]);
                a[2] = *reinterpret_cast<const uint32_t*>(&scr[(m0 + g)     * 264 + kk * 16 + 2 * qd + 8]);
                a[3] = *reinterpret_cast<const uint32_t*>(&scr[(m0 + g + 8) * 264 + kk * 16 + 2 * qd + 8]);
                uint32_t b[2];
                b[0] = *reinterpret_cast<const uint32_t*>(&g_fc2T[(n0 + g) * 256 + kk * 16 + 2 * qd]);
                b[1] = *reinterpret_cast<const uint32_t*>(&g_fc2T[(n0 + g) * 256 + kk * 16 + 2 * qd + 8]);
                mma16816(c, a, b);
            }
            int c0 = n0 + 2 * qd;
            float f0 = fc2b[c0], f1 = fc2b[c0 + 1];
            float* o0 = out + ((size_t)s * 64 + m0 + g)     * 64 + c0;
            float* o1 = out + ((size_t)s * 64 + m0 + g + 8) * 64 + c0;
            o0[0] = c[0] + f0 + xf[(m0 + g)     * 64 + c0];
            o0[1] = c[1] + f1 + xf[(m0 + g)     * 64 + c0 + 1];
            o1[0] = c[2] + f0 + xf[(m0 + g + 8) * 64 + c0];
            o1[1] = c[3] + f1 + xf[(m0 + g + 8) * 64 + c0 + 1];
        }
    }
}

extern "C" void kernel_launch(void* const* d_in, const int* in_sizes, int n_in,
                              void* d_out, int out_size) {
    (void)in_sizes; (void)n_in; (void)out_size;
    const float* x     = (const float*)d_in[0];
    const float* ln1w  = (const float*)d_in[1];
    const float* ln1b  = (const float*)d_in[2];
    const float* wq    = (const float*)d_in[3];
    const float* wk    = (const float*)d_in[4];
    const float* wv    = (const float*)d_in[5];
    const float* projw = (const float*)d_in[6];
    const float* projb = (const float*)d_in[7];
    const float* ln2w  = (const float*)d_in[8];
    const float* ln2b  = (const float*)d_in[9];
    const float* fc1w  = (const float*)d_in[10];
    const float* fc1b  = (const float*)d_in[11];
    const float* fc2w  = (const float*)d_in[12];
    const float* fc2b  = (const float*)d_in[13];

    cudaFuncSetAttribute(block_kernel, cudaFuncAttributeMaxDynamicSharedMemorySize, SMEM_BYTES);

    prep_kernel<<<48, 256>>>(wq, wk, wv, projw, fc1w, fc2w);
    block_kernel<<<SEQS, 128, SMEM_BYTES>>>(x, ln1w, ln1b, projb, ln2w, ln2b,
                                            fc1b, fc2b, (float*)d_out);
}

// round 2
// speedup vs baseline: 1.5556x; 1.5556x over previous
#include <cuda_runtime.h>
#include <cuda_bf16.h>
#include <stdint.h>

#define SEQS 4096

// Dynamic smem layout (bytes):
//  [0,17408)        float xf[64][68]   residual stream (stride 68 to kill bank conflicts)
//  [17408,26624)    bf16  hb[64][72]   LN1 out -> attn out -> LN2 out
//  [26624,44032)    bf16  scr[64][136] q (cols 0..63), k (cols 64..127)
//  [44032,53248)    bf16  vt[8][8][72] V transposed per head: [head][d][s], s-stride 72
#define SMEM_BYTES 53248
#define XF_S 68
#define HB_S 72
#define SCR_S 136
#define VT_S 72

// Fragment-packed bf16 weights: P[nt][lane][kk][2] as u32; per lane-kk u32 j:
//   n = nt*8 + (lane>>2), k = kk*16 + 2*(lane&3) + j*8, value packs W(k,n),W(k+1,n)
__device__ __align__(16) uint32_t g_wqkvP[24 * 32 * 8];   // KK=4 (q nt0..7, k nt8..15, v nt16..23)
__device__ __align__(16) uint32_t g_projP[8 * 32 * 8];    // KK=4
__device__ __align__(16) uint32_t g_fc1P[32 * 32 * 8];    // KK=4
__device__ __align__(16) uint32_t g_fc2P[8 * 32 * 32];    // KK=16

__device__ __forceinline__ uint32_t packbf(float lo, float hi) {
    __nv_bfloat162 t = __floats2bfloat162_rn(lo, hi);
    return *reinterpret_cast<uint32_t*>(&t);
}

__global__ void prep_kernel(const float* __restrict__ wq, const float* __restrict__ wk,
                            const float* __restrict__ wv, const float* __restrict__ projw,
                            const float* __restrict__ fc1w, const float* __restrict__ fc2w) {
    int stride = gridDim.x * blockDim.x;
    int t0 = blockIdx.x * blockDim.x + threadIdx.x;

    // qkv: NT=24, KK=4  (W(k,n): n<64 q, <128 k, else v; head-major cols)
    for (int idx = t0; idx < 24 * 32 * 8; idx += stride) {
        int j = idx & 1, kk = (idx >> 1) & 3, lane = (idx >> 3) & 31, nt = idx >> 8;
        int n = nt * 8 + (lane >> 2);
        int kb = kk * 16 + 2 * (lane & 3) + j * 8;
        float v0, v1;
        if (n < 64)       { int h = n >> 3, d = n & 7; v0 = wq[(h * 64 + kb) * 8 + d]; v1 = wq[(h * 64 + kb + 1) * 8 + d]; }
        else if (n < 128) { int m = n - 64;  int h = m >> 3, d = m & 7; v0 = wk[(h * 64 + kb) * 8 + d]; v1 = wk[(h * 64 + kb + 1) * 8 + d]; }
        else              { int m = n - 128; int h = m >> 3, d = m & 7; v0 = wv[(h * 64 + kb) * 8 + d]; v1 = wv[(h * 64 + kb + 1) * 8 + d]; }
        g_wqkvP[idx] = packbf(v0, v1);
    }
    // proj: NT=8, KK=4, W(k,n) = projw[k*64+n]
    for (int idx = t0; idx < 8 * 32 * 8; idx += stride) {
        int j = idx & 1, kk = (idx >> 1) & 3, lane = (idx >> 3) & 31, nt = idx >> 8;
        int n = nt * 8 + (lane >> 2);
        int kb = kk * 16 + 2 * (lane & 3) + j * 8;
        g_projP[idx] = packbf(projw[kb * 64 + n], projw[(kb + 1) * 64 + n]);
    }
    // fc1: NT=32, KK=4, W(k,n) = fc1w[k*256+n]
    for (int idx = t0; idx < 32 * 32 * 8; idx += stride) {
        int j = idx & 1, kk = (idx >> 1) & 3, lane = (idx >> 3) & 31, nt = idx >> 8;
        int n = nt * 8 + (lane >> 2);
        int kb = kk * 16 + 2 * (lane & 3) + j * 8;
        g_fc1P[idx] = packbf(fc1w[kb * 256 + n], fc1w[(kb + 1) * 256 + n]);
    }
    // fc2: NT=8, KK=16, W(k,n) = fc2w[k*64+n]
    for (int idx = t0; idx < 8 * 32 * 32; idx += stride) {
        int j = idx & 1, kk = (idx >> 1) & 15, lane = (idx >> 5) & 31, nt = idx >> 10;
        int n = nt * 8 + (lane >> 2);
        int kb = kk * 16 + 2 * (lane & 3) + j * 8;
        g_fc2P[idx] = packbf(fc2w[kb * 64 + n], fc2w[(kb + 1) * 64 + n]);
    }
}

__device__ __forceinline__ void mma16816(float* c, const uint32_t* a, const uint32_t* b) {
    asm volatile(
        "mma.sync.aligned.m16n8k16.row.col.f32.bf16.bf16.f32 "
        "{%0,%1,%2,%3}, {%4,%5,%6,%7}, {%8,%9}, {%0,%1,%2,%3};\n"
        : "+f"(c[0]), "+f"(c[1]), "+f"(c[2]), "+f"(c[3])
        : "r"(a[0]), "r"(a[1]), "r"(a[2]), "r"(a[3]), "r"(b[0]), "r"(b[1]));
}

__device__ __forceinline__ void mma1688(float* c, const uint32_t* a, uint32_t b) {
    asm volatile(
        "mma.sync.aligned.m16n8k8.row.col.f32.bf16.bf16.f32 "
        "{%0,%1,%2,%3}, {%4,%5}, {%6}, {%0,%1,%2,%3};\n"
        : "+f"(c[0]), "+f"(c[1]), "+f"(c[2]), "+f"(c[3])
        : "r"(a[0]), "r"(a[1]), "r"(b));
}

__global__ __launch_bounds__(128, 4) void block_kernel(
    const float* __restrict__ x,
    const float* __restrict__ ln1w, const float* __restrict__ ln1b,
    const float* __restrict__ projb,
    const float* __restrict__ ln2w, const float* __restrict__ ln2b,
    const float* __restrict__ fc1b, const float* __restrict__ fc2b,
    float* __restrict__ out)
{
    extern __shared__ char smraw[];
    float* xf            = reinterpret_cast<float*>(smraw);                       // [64][68]
    __nv_bfloat16* hb    = reinterpret_cast<__nv_bfloat16*>(smraw + 17408);       // [64][72]
    __nv_bfloat16* scr   = reinterpret_cast<__nv_bfloat16*>(smraw + 26624);       // [64][136]
    __nv_bfloat16* vt    = reinterpret_cast<__nv_bfloat16*>(smraw + 44032);       // [8][8][72]

    const int tid  = threadIdx.x;
    const int w    = tid >> 5;
    const int lane = tid & 31;
    const int g    = lane >> 2;
    const int qd   = lane & 3;
    const int s    = blockIdx.x;
    const int m0   = w * 16;

    // ---- load x tile [64][64] -> xf (stride 68) ----
    {
        const float4* xg = reinterpret_cast<const float4*>(x + (size_t)s * 64 * 64);
        int row = tid >> 1, c0 = (tid & 1) * 32;
#pragma unroll
        for (int i = 0; i < 8; ++i) {
            float4 v = xg[row * 16 + (c0 >> 2) + i];
            *reinterpret_cast<float4*>(&xf[row * XF_S + c0 + 4 * i]) = v;
        }
    }
    __syncthreads();

    // ---- LN1 (own 16 rows) -> hb ----
    {
        float w0 = ln1w[lane], w1 = ln1w[lane + 32];
        float b0 = ln1b[lane], b1 = ln1b[lane + 32];
        for (int r = m0; r < m0 + 16; ++r) {
            float v0 = xf[r * XF_S + lane], v1 = xf[r * XF_S + lane + 32];
            float sum = v0 + v1, sq = v0 * v0 + v1 * v1;
#pragma unroll
            for (int o = 16; o; o >>= 1) {
                sum += __shfl_xor_sync(0xffffffffu, sum, o);
                sq  += __shfl_xor_sync(0xffffffffu, sq, o);
            }
            float mu = sum * 0.015625f;
            float rs = rsqrtf(sq * 0.015625f - mu * mu + 1e-5f);
            hb[r * HB_S + lane]      = __float2bfloat16((v0 - mu) * rs * w0 + b0);
            hb[r * HB_S + lane + 32] = __float2bfloat16((v1 - mu) * rs * w1 + b1);
        }
    }
    __syncwarp();

    // ---- QKV GEMM: rows m0..m0+15, all 192 cols. q,k -> scr; v -> vt (transposed) ----
    {
        uint32_t a[4][4];
#pragma unroll
        for (int kk = 0; kk < 4; ++kk) {
            int k0 = kk * 16;
            a[kk][0] = *reinterpret_cast<const uint32_t*>(&hb[(m0 + g)     * HB_S + k0 + 2 * qd]);
            a[kk][1] = *reinterpret_cast<const uint32_t*>(&hb[(m0 + g + 8) * HB_S + k0 + 2 * qd]);
            a[kk][2] = *reinterpret_cast<const uint32_t*>(&hb[(m0 + g)     * HB_S + k0 + 2 * qd + 8]);
            a[kk][3] = *reinterpret_cast<const uint32_t*>(&hb[(m0 + g + 8) * HB_S + k0 + 2 * qd + 8]);
        }
#pragma unroll 4
        for (int nt = 0; nt < 24; ++nt) {
            const uint4* p = reinterpret_cast<const uint4*>(&g_wqkvP[(nt * 32 + lane) * 8]);
            uint4 b01 = p[0], b23 = p[1];
            float c[4] = {0.f, 0.f, 0.f, 0.f};
            mma16816(c, a[0], &b01.x);
            mma16816(c, a[1], &b01.z);
            mma16816(c, a[2], &b23.x);
            mma16816(c, a[3], &b23.z);
            if (nt < 16) {
                int n0 = nt * 8;
                *reinterpret_cast<uint32_t*>(&scr[(m0 + g)     * SCR_S + n0 + 2 * qd]) = packbf(c[0], c[1]);
                *reinterpret_cast<uint32_t*>(&scr[(m0 + g + 8) * SCR_S + n0 + 2 * qd]) = packbf(c[2], c[3]);
            } else {
                int head = nt - 16;
                __nv_bfloat16* vh = vt + head * 8 * VT_S;
                vh[(2 * qd)     * VT_S + m0 + g]     = __float2bfloat16(c[0]);
                vh[(2 * qd + 1) * VT_S + m0 + g]     = __float2bfloat16(c[1]);
                vh[(2 * qd)     * VT_S + m0 + g + 8] = __float2bfloat16(c[2]);
                vh[(2 * qd + 1) * VT_S + m0 + g + 8] = __float2bfloat16(c[3]);
            }
        }
    }
    __syncthreads();

    // ---- attention: warp handles heads 2w, 2w+1 over all 64 rows; out -> hb ----
#pragma unroll
    for (int hh = 0; hh < 2; ++hh) {
        const int hd = w * 2 + hh;
        const int qcol = hd * 8, kcol = 64 + hd * 8;
        const __nv_bfloat16* vh = vt + hd * 8 * VT_S;
#pragma unroll
        for (int mt = 0; mt < 4; ++mt) {
            const int t0 = mt * 16;
            const int ntm = 2 * mt + 1;
            uint32_t aq[2];
            aq[0] = *reinterpret_cast<const uint32_t*>(&scr[(t0 + g)     * SCR_S + qcol + 2 * qd]);
            aq[1] = *reinterpret_cast<const uint32_t*>(&scr[(t0 + g + 8) * SCR_S + qcol + 2 * qd]);
            float sc[8][4];
#pragma unroll
            for (int nt = 0; nt < 8; ++nt) {
                if (nt > ntm) continue;
                sc[nt][0] = sc[nt][1] = sc[nt][2] = sc[nt][3] = 0.f;
                uint32_t bk = *reinterpret_cast<const uint32_t*>(&scr[(nt * 8 + g) * SCR_S + kcol + 2 * qd]);
                mma1688(sc[nt], aq, bk);
            }
            const int rlo = t0 + g, rhi = t0 + g + 8;
            float mlo = -1e30f, mhi = -1e30f;
#pragma unroll
            for (int nt = 0; nt < 8; ++nt) {
                if (nt > ntm) continue;
#pragma unroll
                for (int e = 0; e < 2; ++e) {
                    int col = nt * 8 + 2 * qd + e;
                    float v0 = sc[nt][e] * 0.125f;     if (col > rlo) v0 = -1e30f;
                    float v1 = sc[nt][2 + e] * 0.125f; if (col > rhi) v1 = -1e30f;
                    sc[nt][e] = v0; sc[nt][2 + e] = v1;
                    mlo = fmaxf(mlo, v0); mhi = fmaxf(mhi, v1);
                }
            }
            mlo = fmaxf(mlo, __shfl_xor_sync(0xffffffffu, mlo, 1));
            mlo = fmaxf(mlo, __shfl_xor_sync(0xffffffffu, mlo, 2));
            mhi = fmaxf(mhi, __shfl_xor_sync(0xffffffffu, mhi, 1));
            mhi = fmaxf(mhi, __shfl_xor_sync(0xffffffffu, mhi, 2));
            float slo = 0.f, shi = 0.f;
#pragma unroll
            for (int nt = 0; nt < 8; ++nt) {
                if (nt > ntm) continue;
#pragma unroll
                for (int e = 0; e < 2; ++e) {
                    float p0 = __expf(sc[nt][e] - mlo);
                    float p1 = __expf(sc[nt][2 + e] - mhi);
                    sc[nt][e] = p0; sc[nt][2 + e] = p1;
                    slo += p0; shi += p1;
                }
            }
            slo += __shfl_xor_sync(0xffffffffu, slo, 1);
            slo += __shfl_xor_sync(0xffffffffu, slo, 2);
            shi += __shfl_xor_sync(0xffffffffu, shi, 1);
            shi += __shfl_xor_sync(0xffffffffu, shi, 2);
            float acc[4] = {0.f, 0.f, 0.f, 0.f};
#pragma unroll
            for (int kc = 0; kc < 4; ++kc) {
                if (kc > mt) continue;
                uint32_t pa[4];
                pa[0] = packbf(sc[2 * kc][0],     sc[2 * kc][1]);
                pa[1] = packbf(sc[2 * kc][2],     sc[2 * kc][3]);
                pa[2] = packbf(sc[2 * kc + 1][0], sc[2 * kc + 1][1]);
                pa[3] = packbf(sc[2 * kc + 1][2], sc[2 * kc + 1][3]);
                const int sb = kc * 16;
                uint32_t b[2];
                b[0] = *reinterpret_cast<const uint32_t*>(&vh[g * VT_S + sb + 2 * qd]);
                b[1] = *reinterpret_cast<const uint32_t*>(&vh[g * VT_S + sb + 2 * qd + 8]);
                mma16816(acc, pa, b);
            }
            float ilo = 1.f / slo, ihi = 1.f / shi;
            *reinterpret_cast<uint32_t*>(&hb[(t0 + g)     * HB_S + qcol + 2 * qd]) = packbf(acc[0] * ilo, acc[1] * ilo);
            *reinterpret_cast<uint32_t*>(&hb[(t0 + g + 8) * HB_S + qcol + 2 * qd]) = packbf(acc[2] * ihi, acc[3] * ihi);
        }
    }
    __syncthreads();

    // ---- proj + residual into xf ----
    {
        uint32_t a[4][4];
#pragma unroll
        for (int kk = 0; kk < 4; ++kk) {
            int k0 = kk * 16;
            a[kk][0] = *reinterpret_cast<const uint32_t*>(&hb[(m0 + g)     * HB_S + k0 + 2 * qd]);
            a[kk][1] = *reinterpret_cast<const uint32_t*>(&hb[(m0 + g + 8) * HB_S + k0 + 2 * qd]);
            a[kk][2] = *reinterpret_cast<const uint32_t*>(&hb[(m0 + g)     * HB_S + k0 + 2 * qd + 8]);
            a[kk][3] = *reinterpret_cast<const uint32_t*>(&hb[(m0 + g + 8) * HB_S + k0 + 2 * qd + 8]);
        }
#pragma unroll
        for (int nt = 0; nt < 8; ++nt) {
            const uint4* p = reinterpret_cast<const uint4*>(&g_projP[(nt * 32 + lane) * 8]);
            uint4 b01 = p[0], b23 = p[1];
            float c[4] = {0.f, 0.f, 0.f, 0.f};
            mma16816(c, a[0], &b01.x);
            mma16816(c, a[1], &b01.z);
            mma16816(c, a[2], &b23.x);
            mma16816(c, a[3], &b23.z);
            int c0 = nt * 8 + 2 * qd;
            float pb0 = projb[c0], pb1 = projb[c0 + 1];
            float2* p0 = reinterpret_cast<float2*>(&xf[(m0 + g)     * XF_S + c0]);
            float2* p1 = reinterpret_cast<float2*>(&xf[(m0 + g + 8) * XF_S + c0]);
            float2 v0 = *p0, v1 = *p1;
            v0.x += c[0] + pb0; v0.y += c[1] + pb1;
            v1.x += c[2] + pb0; v1.y += c[3] + pb1;
            *p0 = v0; *p1 = v1;
        }
    }
    __syncwarp();

    // ---- LN2 -> hb ----
    {
        float w0 = ln2w[lane], w1 = ln2w[lane + 32];
        float b0 = ln2b[lane], b1 = ln2b[lane + 32];
        for (int r = m0; r < m0 + 16; ++r) {
            float v0 = xf[r * XF_S + lane], v1 = xf[r * XF_S + lane + 32];
            float sum = v0 + v1, sq = v0 * v0 + v1 * v1;
#pragma unroll
            for (int o = 16; o; o >>= 1) {
                sum += __shfl_xor_sync(0xffffffffu, sum, o);
                sq  += __shfl_xor_sync(0xffffffffu, sq, o);
            }
            float mu = sum * 0.015625f;
            float rs = rsqrtf(sq * 0.015625f - mu * mu + 1e-5f);
            hb[r * HB_S + lane]      = __float2bfloat16((v0 - mu) * rs * w0 + b0);
            hb[r * HB_S + lane + 32] = __float2bfloat16((v1 - mu) * rs * w1 + b1);
        }
    }
    __syncwarp();

    // ---- fc1 + relu fused to registers (A-fragments for fc2) ----
    uint32_t apk[16][4];
    {
        uint32_t a[4][4];
#pragma unroll
        for (int kk = 0; kk < 4; ++kk) {
            int k0 = kk * 16;
            a[kk][0] = *reinterpret_cast<const uint32_t*>(&hb[(m0 + g)     * HB_S + k0 + 2 * qd]);
            a[kk][1] = *reinterpret_cast<const uint32_t*>(&hb[(m0 + g + 8) * HB_S + k0 + 2 * qd]);
            a[kk][2] = *reinterpret_cast<const uint32_t*>(&hb[(m0 + g)     * HB_S + k0 + 2 * qd + 8]);
            a[kk][3] = *reinterpret_cast<const uint32_t*>(&hb[(m0 + g + 8) * HB_S + k0 + 2 * qd + 8]);
        }
#pragma unroll
        for (int kk = 0; kk < 16; ++kk) {
#pragma unroll
            for (int half = 0; half < 2; ++half) {
                int nt = 2 * kk + half;  // fc1 n-tile, n0 = nt*8
                const uint4* p = reinterpret_cast<const uint4*>(&g_fc1P[(nt * 32 + lane) * 8]);
                uint4 b01 = p[0], b23 = p[1];
                float c[4] = {0.f, 0.f, 0.f, 0.f};
                mma16816(c, a[0], &b01.x);
                mma16816(c, a[1], &b01.z);
                mma16816(c, a[2], &b23.x);
                mma16816(c, a[3], &b23.z);
                int c0 = nt * 8 + 2 * qd;
                float f0 = __ldg(&fc1b[c0]), f1 = __ldg(&fc1b[c0 + 1]);
                apk[kk][2 * half]     = packbf(fmaxf(c[0] + f0, 0.f), fmaxf(c[1] + f1, 0.f));
                apk[kk][2 * half + 1] = packbf(fmaxf(c[2] + f0, 0.f), fmaxf(c[3] + f1, 0.f));
            }
        }
    }

    // ---- fc2 + residual -> out ----
    {
#pragma unroll
        for (int nt = 0; nt < 8; ++nt) {
            const uint4* p = reinterpret_cast<const uint4*>(&g_fc2P[(nt * 32 + lane) * 32]);
            float c[4] = {0.f, 0.f, 0.f, 0.f};
#pragma unroll
            for (int kk = 0; kk < 16; kk += 2) {
                uint4 bb = p[kk >> 1];
                mma16816(c, apk[kk],     &bb.x);
                mma16816(c, apk[kk + 1], &bb.z);
            }
            int c0 = nt * 8 + 2 * qd;
            float f0 = fc2b[c0], f1 = fc2b[c0 + 1];
            float2 x0 = *reinterpret_cast<const float2*>(&xf[(m0 + g)     * XF_S + c0]);
            float2 x1 = *reinterpret_cast<const float2*>(&xf[(m0 + g + 8) * XF_S + c0]);
            float2 o0, o1;
            o0.x = c[0] + f0 + x0.x; o0.y = c[1] + f1 + x0.y;
            o1.x = c[2] + f0 + x1.x; o1.y = c[3] + f1 + x1.y;
            *reinterpret_cast<float2*>(out + ((size_t)s * 64 + m0 + g)     * 64 + c0) = o0;
            *reinterpret_cast<float2*>(out + ((size_t)s * 64 + m0 + g + 8) * 64 + c0) = o1;
        }
    }
}

extern "C" void kernel_launch(void* const* d_in, const int* in_sizes, int n_in,
                              void* d_out, int out_size) {
    (void)in_sizes; (void)n_in; (void)out_size;
    const float* x     = (const float*)d_in[0];
    const float* ln1w  = (const float*)d_in[1];
    const float* ln1b  = (const float*)d_in[2];
    const float* wq    = (const float*)d_in[3];
    const float* wk    = (const float*)d_in[4];
    const float* wv    = (const float*)d_in[5];
    const float* projw = (const float*)d_in[6];
    const float* projb = (const float*)d_in[7];
    const float* ln2w  = (const float*)d_in[8];
    const float* ln2b  = (const float*)d_in[9];
    const float* fc1w  = (const float*)d_in[10];
    const float* fc1b  = (const float*)d_in[11];
    const float* fc2w  = (const float*)d_in[12];
    const float* fc2b  = (const float*)d_in[13];

    cudaFuncSetAttribute(block_kernel, cudaFuncAttributeMaxDynamicSharedMemorySize, SMEM_BYTES);

    prep_kernel<<<32, 256>>>(wq, wk, wv, projw, fc1w, fc2w);
    block_kernel<<<SEQS, 128, SMEM_BYTES>>>(x, ln1w, ln1b, projb, ln2w, ln2b,
                                            fc1b, fc2b, (float*)d_out);
}

// round 3
// speedup vs baseline: 2.3874x; 1.5348x over previous
#include <cuda_runtime.h>
#include <cuda_bf16.h>
#include <stdint.h>

#define SEQS 4096

// Dynamic smem layout (bytes):
//  [0,17408)        float xf[64][68]   residual stream
//  [17408,26624)    bf16  hb[64][72]   LN1 out -> attn out -> LN2 out
//  [26624,44032)    bf16  scr[64][136] q (cols 0..63), k (cols 64..127)
//  [44032,53248)    bf16  vt[8][8][72] V transposed per head: [head][d][s]
#define SMEM_BYTES 53248
#define XF_S 68
#define HB_S 72
#define SCR_S 136
#define VT_S 72

// Fragment-packed bf16 weights, coalesced blocks:
//   layout [nt][u][lane][c], c in 0..3 (one uint4 per lane per u-block).
//   kk = 2u + (c>>1), j = c&1; n = nt*8 + (lane>>2); k = kk*16 + 2*(lane&3) + 8*j
//   u32 packs W(k,n), W(k+1,n).
__device__ __align__(16) uint32_t g_wqkvP[24 * 2 * 32 * 4];   // KKH=2 (q nt0..7, k nt8..15, v nt16..23)
__device__ __align__(16) uint32_t g_projP[8 * 2 * 32 * 4];    // KKH=2
__device__ __align__(16) uint32_t g_fc1P[32 * 2 * 32 * 4];    // KKH=2
__device__ __align__(16) uint32_t g_fc2P[8 * 8 * 32 * 4];     // KKH=8

__device__ __forceinline__ uint32_t packbf(float lo, float hi) {
    __nv_bfloat162 t = __floats2bfloat162_rn(lo, hi);
    return *reinterpret_cast<uint32_t*>(&t);
}

__global__ void prep_kernel(const float* __restrict__ wq, const float* __restrict__ wk,
                            const float* __restrict__ wv, const float* __restrict__ projw,
                            const float* __restrict__ fc1w, const float* __restrict__ fc2w) {
    int stride = gridDim.x * blockDim.x;
    int t0 = blockIdx.x * blockDim.x + threadIdx.x;

    // qkv: NT=24, KKH=2
    for (int idx = t0; idx < 24 * 2 * 32 * 4; idx += stride) {
        int c = idx & 3, lane = (idx >> 2) & 31, u = (idx >> 7) & 1, nt = idx >> 8;
        int kk = 2 * u + (c >> 1), j = c & 1;
        int n = nt * 8 + (lane >> 2);
        int kb = kk * 16 + 2 * (lane & 3) + 8 * j;
        float v0, v1;
        if (n < 64)       { int h = n >> 3, d = n & 7; v0 = wq[(h * 64 + kb) * 8 + d]; v1 = wq[(h * 64 + kb + 1) * 8 + d]; }
        else if (n < 128) { int m = n - 64;  int h = m >> 3, d = m & 7; v0 = wk[(h * 64 + kb) * 8 + d]; v1 = wk[(h * 64 + kb + 1) * 8 + d]; }
        else              { int m = n - 128; int h = m >> 3, d = m & 7; v0 = wv[(h * 64 + kb) * 8 + d]; v1 = wv[(h * 64 + kb + 1) * 8 + d]; }
        g_wqkvP[idx] = packbf(v0, v1);
    }
    // proj: NT=8, KKH=2
    for (int idx = t0; idx < 8 * 2 * 32 * 4; idx += stride) {
        int c = idx & 3, lane = (idx >> 2) & 31, u = (idx >> 7) & 1, nt = idx >> 8;
        int kk = 2 * u + (c >> 1), j = c & 1;
        int n = nt * 8 + (lane >> 2);
        int kb = kk * 16 + 2 * (lane & 3) + 8 * j;
        g_projP[idx] = packbf(projw[kb * 64 + n], projw[(kb + 1) * 64 + n]);
    }
    // fc1: NT=32, KKH=2
    for (int idx = t0; idx < 32 * 2 * 32 * 4; idx += stride) {
        int c = idx & 3, lane = (idx >> 2) & 31, u = (idx >> 7) & 1, nt = idx >> 8;
        int kk = 2 * u + (c >> 1), j = c & 1;
        int n = nt * 8 + (lane >> 2);
        int kb = kk * 16 + 2 * (lane & 3) + 8 * j;
        g_fc1P[idx] = packbf(fc1w[kb * 256 + n], fc1w[(kb + 1) * 256 + n]);
    }
    // fc2: NT=8, KKH=8
    for (int idx = t0; idx < 8 * 8 * 32 * 4; idx += stride) {
        int c = idx & 3, lane = (idx >> 2) & 31, u = (idx >> 7) & 7, nt = idx >> 10;
        int kk = 2 * u + (c >> 1), j = c & 1;
        int n = nt * 8 + (lane >> 2);
        int kb = kk * 16 + 2 * (lane & 3) + 8 * j;
        g_fc2P[idx] = packbf(fc2w[kb * 64 + n], fc2w[(kb + 1) * 64 + n]);
    }
}

__device__ __forceinline__ void mma16816(float* c, const uint32_t* a, const uint32_t* b) {
    asm volatile(
        "mma.sync.aligned.m16n8k16.row.col.f32.bf16.bf16.f32 "
        "{%0,%1,%2,%3}, {%4,%5,%6,%7}, {%8,%9}, {%0,%1,%2,%3};\n"
        : "+f"(c[0]), "+f"(c[1]), "+f"(c[2]), "+f"(c[3])
        : "r"(a[0]), "r"(a[1]), "r"(a[2]), "r"(a[3]), "r"(b[0]), "r"(b[1]));
}

__device__ __forceinline__ void mma1688(float* c, const uint32_t* a, uint32_t b) {
    asm volatile(
        "mma.sync.aligned.m16n8k8.row.col.f32.bf16.bf16.f32 "
        "{%0,%1,%2,%3}, {%4,%5}, {%6}, {%0,%1,%2,%3};\n"
        : "+f"(c[0]), "+f"(c[1]), "+f"(c[2]), "+f"(c[3])
        : "r"(a[0]), "r"(a[1]), "r"(b));
}

__global__ __launch_bounds__(128, 4) void block_kernel(
    const float* __restrict__ x,
    const float* __restrict__ ln1w, const float* __restrict__ ln1b,
    const float* __restrict__ projb,
    const float* __restrict__ ln2w, const float* __restrict__ ln2b,
    const float* __restrict__ fc1b, const float* __restrict__ fc2b,
    float* __restrict__ out)
{
    extern __shared__ char smraw[];
    float* xf            = reinterpret_cast<float*>(smraw);                       // [64][68]
    __nv_bfloat16* hb    = reinterpret_cast<__nv_bfloat16*>(smraw + 17408);       // [64][72]
    __nv_bfloat16* scr   = reinterpret_cast<__nv_bfloat16*>(smraw + 26624);       // [64][136]
    __nv_bfloat16* vt    = reinterpret_cast<__nv_bfloat16*>(smraw + 44032);       // [8][8][72]

    const int tid  = threadIdx.x;
    const int w    = tid >> 5;
    const int lane = tid & 31;
    const int g    = lane >> 2;
    const int qd   = lane & 3;
    const int s    = blockIdx.x;
    const int m0   = w * 16;

    // ---- load x tile [64][64] -> xf (stride 68) ----
    {
        const float4* xg = reinterpret_cast<const float4*>(x + (size_t)s * 64 * 64);
        int row = tid >> 1, c0 = (tid & 1) * 32;
#pragma unroll
        for (int i = 0; i < 8; ++i) {
            float4 v = xg[row * 16 + (c0 >> 2) + i];
            *reinterpret_cast<float4*>(&xf[row * XF_S + c0 + 4 * i]) = v;
        }
    }
    __syncthreads();

    // ---- LN1 (own 16 rows) -> hb; lane owns cols 2l, 2l+1 ----
    {
        float2 lw = *reinterpret_cast<const float2*>(&ln1w[2 * lane]);
        float2 lb = *reinterpret_cast<const float2*>(&ln1b[2 * lane]);
        for (int r = m0; r < m0 + 16; ++r) {
            float2 v = *reinterpret_cast<const float2*>(&xf[r * XF_S + 2 * lane]);
            float sum = v.x + v.y, sq = v.x * v.x + v.y * v.y;
#pragma unroll
            for (int o = 16; o; o >>= 1) {
                sum += __shfl_xor_sync(0xffffffffu, sum, o);
                sq  += __shfl_xor_sync(0xffffffffu, sq, o);
            }
            float mu = sum * 0.015625f;
            float rs = rsqrtf(sq * 0.015625f - mu * mu + 1e-5f);
            *reinterpret_cast<uint32_t*>(&hb[r * HB_S + 2 * lane]) =
                packbf((v.x - mu) * rs * lw.x + lb.x, (v.y - mu) * rs * lw.y + lb.y);
        }
    }
    __syncwarp();

    // ---- QKV GEMM: rows m0..m0+15, all 192 cols. q,k -> scr; v -> vt (transposed) ----
    {
        uint32_t a[4][4];
#pragma unroll
        for (int kk = 0; kk < 4; ++kk) {
            int k0 = kk * 16;
            a[kk][0] = *reinterpret_cast<const uint32_t*>(&hb[(m0 + g)     * HB_S + k0 + 2 * qd]);
            a[kk][1] = *reinterpret_cast<const uint32_t*>(&hb[(m0 + g + 8) * HB_S + k0 + 2 * qd]);
            a[kk][2] = *reinterpret_cast<const uint32_t*>(&hb[(m0 + g)     * HB_S + k0 + 2 * qd + 8]);
            a[kk][3] = *reinterpret_cast<const uint32_t*>(&hb[(m0 + g + 8) * HB_S + k0 + 2 * qd + 8]);
        }
#pragma unroll 4
        for (int nt = 0; nt < 24; ++nt) {
            uint4 b01 = *reinterpret_cast<const uint4*>(&g_wqkvP[(nt * 64 + lane) * 4]);
            uint4 b23 = *reinterpret_cast<const uint4*>(&g_wqkvP[(nt * 64 + 32 + lane) * 4]);
            float c[4] = {0.f, 0.f, 0.f, 0.f};
            mma16816(c, a[0], &b01.x);
            mma16816(c, a[1], &b01.z);
            mma16816(c, a[2], &b23.x);
            mma16816(c, a[3], &b23.z);
            if (nt < 16) {
                int n0 = nt * 8;
                *reinterpret_cast<uint32_t*>(&scr[(m0 + g)     * SCR_S + n0 + 2 * qd]) = packbf(c[0], c[1]);
                *reinterpret_cast<uint32_t*>(&scr[(m0 + g + 8) * SCR_S + n0 + 2 * qd]) = packbf(c[2], c[3]);
            } else {
                int head = nt - 16;
                __nv_bfloat16* vh = vt + head * 8 * VT_S;
                vh[(2 * qd)     * VT_S + m0 + g]     = __float2bfloat16(c[0]);
                vh[(2 * qd + 1) * VT_S + m0 + g]     = __float2bfloat16(c[1]);
                vh[(2 * qd)     * VT_S + m0 + g + 8] = __float2bfloat16(c[2]);
                vh[(2 * qd + 1) * VT_S + m0 + g + 8] = __float2bfloat16(c[3]);
            }
        }
    }
    __syncthreads();

    // ---- attention: warp handles heads 2w, 2w+1 over all 64 rows; out -> hb ----
#pragma unroll
    for (int hh = 0; hh < 2; ++hh) {
        const int hd = w * 2 + hh;
        const int qcol = hd * 8, kcol = 64 + hd * 8;
        const __nv_bfloat16* vh = vt + hd * 8 * VT_S;
#pragma unroll
        for (int mt = 0; mt < 4; ++mt) {
            const int t0 = mt * 16;
            const int ntm = 2 * mt + 1;
            uint32_t aq[2];
            aq[0] = *reinterpret_cast<const uint32_t*>(&scr[(t0 + g)     * SCR_S + qcol + 2 * qd]);
            aq[1] = *reinterpret_cast<const uint32_t*>(&scr[(t0 + g + 8) * SCR_S + qcol + 2 * qd]);
            float sc[8][4];
#pragma unroll
            for (int nt = 0; nt < 8; ++nt) {
                if (nt > ntm) continue;
                sc[nt][0] = sc[nt][1] = sc[nt][2] = sc[nt][3] = 0.f;
                uint32_t bk = *reinterpret_cast<const uint32_t*>(&scr[(nt * 8 + g) * SCR_S + kcol + 2 * qd]);
                mma1688(sc[nt], aq, bk);
            }
            const int rlo = t0 + g, rhi = t0 + g + 8;
            float mlo = -1e30f, mhi = -1e30f;
#pragma unroll
            for (int nt = 0; nt < 8; ++nt) {
                if (nt > ntm) continue;
#pragma unroll
                for (int e = 0; e < 2; ++e) {
                    int col = nt * 8 + 2 * qd + e;
                    float v0 = sc[nt][e] * 0.125f;     if (col > rlo) v0 = -1e30f;
                    float v1 = sc[nt][2 + e] * 0.125f; if (col > rhi) v1 = -1e30f;
                    sc[nt][e] = v0; sc[nt][2 + e] = v1;
                    mlo = fmaxf(mlo, v0); mhi = fmaxf(mhi, v1);
                }
            }
            mlo = fmaxf(mlo, __shfl_xor_sync(0xffffffffu, mlo, 1));
            mlo = fmaxf(mlo, __shfl_xor_sync(0xffffffffu, mlo, 2));
            mhi = fmaxf(mhi, __shfl_xor_sync(0xffffffffu, mhi, 1));
            mhi = fmaxf(mhi, __shfl_xor_sync(0xffffffffu, mhi, 2));
            float slo = 0.f, shi = 0.f;
#pragma unroll
            for (int nt = 0; nt < 8; ++nt) {
                if (nt > ntm) continue;
#pragma unroll
                for (int e = 0; e < 2; ++e) {
                    float p0 = __expf(sc[nt][e] - mlo);
                    float p1 = __expf(sc[nt][2 + e] - mhi);
                    sc[nt][e] = p0; sc[nt][2 + e] = p1;
                    slo += p0; shi += p1;
                }
            }
            slo += __shfl_xor_sync(0xffffffffu, slo, 1);
            slo += __shfl_xor_sync(0xffffffffu, slo, 2);
            shi += __shfl_xor_sync(0xffffffffu, shi, 1);
            shi += __shfl_xor_sync(0xffffffffu, shi, 2);
            float acc[4] = {0.f, 0.f, 0.f, 0.f};
#pragma unroll
            for (int kc = 0; kc < 4; ++kc) {
                if (kc > mt) continue;
                uint32_t pa[4];
                pa[0] = packbf(sc[2 * kc][0],     sc[2 * kc][1]);
                pa[1] = packbf(sc[2 * kc][2],     sc[2 * kc][3]);
                pa[2] = packbf(sc[2 * kc + 1][0], sc[2 * kc + 1][1]);
                pa[3] = packbf(sc[2 * kc + 1][2], sc[2 * kc + 1][3]);
                const int sb = kc * 16;
                uint32_t b[2];
                b[0] = *reinterpret_cast<const uint32_t*>(&vh[g * VT_S + sb + 2 * qd]);
                b[1] = *reinterpret_cast<const uint32_t*>(&vh[g * VT_S + sb + 2 * qd + 8]);
                mma16816(acc, pa, b);
            }
            float ilo = 1.f / slo, ihi = 1.f / shi;
            *reinterpret_cast<uint32_t*>(&hb[(t0 + g)     * HB_S + qcol + 2 * qd]) = packbf(acc[0] * ilo, acc[1] * ilo);
            *reinterpret_cast<uint32_t*>(&hb[(t0 + g + 8) * HB_S + qcol + 2 * qd]) = packbf(acc[2] * ihi, acc[3] * ihi);
        }
    }
    __syncthreads();

    // ---- proj + residual into xf ----
    {
        uint32_t a[4][4];
#pragma unroll
        for (int kk = 0; kk < 4; ++kk) {
            int k0 = kk * 16;
            a[kk][0] = *reinterpret_cast<const uint32_t*>(&hb[(m0 + g)     * HB_S + k0 + 2 * qd]);
            a[kk][1] = *reinterpret_cast<const uint32_t*>(&hb[(m0 + g + 8) * HB_S + k0 + 2 * qd]);
            a[kk][2] = *reinterpret_cast<const uint32_t*>(&hb[(m0 + g)     * HB_S + k0 + 2 * qd + 8]);
            a[kk][3] = *reinterpret_cast<const uint32_t*>(&hb[(m0 + g + 8) * HB_S + k0 + 2 * qd + 8]);
        }
#pragma unroll
        for (int nt = 0; nt < 8; ++nt) {
            uint4 b01 = *reinterpret_cast<const uint4*>(&g_projP[(nt * 64 + lane) * 4]);
            uint4 b23 = *reinterpret_cast<const uint4*>(&g_projP[(nt * 64 + 32 + lane) * 4]);
            float c[4] = {0.f, 0.f, 0.f, 0.f};
            mma16816(c, a[0], &b01.x);
            mma16816(c, a[1], &b01.z);
            mma16816(c, a[2], &b23.x);
            mma16816(c, a[3], &b23.z);
            int c0 = nt * 8 + 2 * qd;
            float pb0 = projb[c0], pb1 = projb[c0 + 1];
            float2* p0 = reinterpret_cast<float2*>(&xf[(m0 + g)     * XF_S + c0]);
            float2* p1 = reinterpret_cast<float2*>(&xf[(m0 + g + 8) * XF_S + c0]);
            float2 v0 = *p0, v1 = *p1;
            v0.x += c[0] + pb0; v0.y += c[1] + pb1;
            v1.x += c[2] + pb0; v1.y += c[3] + pb1;
            *p0 = v0; *p1 = v1;
        }
    }
    __syncwarp();

    // ---- LN2 -> hb ----
    {
        float2 lw = *reinterpret_cast<const float2*>(&ln2w[2 * lane]);
        float2 lb = *reinterpret_cast<const float2*>(&ln2b[2 * lane]);
        for (int r = m0; r < m0 + 16; ++r) {
            float2 v = *reinterpret_cast<const float2*>(&xf[r * XF_S + 2 * lane]);
            float sum = v.x + v.y, sq = v.x * v.x + v.y * v.y;
#pragma unroll
            for (int o = 16; o; o >>= 1) {
                sum += __shfl_xor_sync(0xffffffffu, sum, o);
                sq  += __shfl_xor_sync(0xffffffffu, sq, o);
            }
            float mu = sum * 0.015625f;
            float rs = rsqrtf(sq * 0.015625f - mu * mu + 1e-5f);
            *reinterpret_cast<uint32_t*>(&hb[r * HB_S + 2 * lane]) =
                packbf((v.x - mu) * rs * lw.x + lb.x, (v.y - mu) * rs * lw.y + lb.y);
        }
    }
    __syncwarp();

    // ---- fc1 + relu fused to registers (A-fragments for fc2) ----
    uint32_t apk[16][4];
    {
        uint32_t a[4][4];
#pragma unroll
        for (int kk = 0; kk < 4; ++kk) {
            int k0 = kk * 16;
            a[kk][0] = *reinterpret_cast<const uint32_t*>(&hb[(m0 + g)     * HB_S + k0 + 2 * qd]);
            a[kk][1] = *reinterpret_cast<const uint32_t*>(&hb[(m0 + g + 8) * HB_S + k0 + 2 * qd]);
            a[kk][2] = *reinterpret_cast<const uint32_t*>(&hb[(m0 + g)     * HB_S + k0 + 2 * qd + 8]);
            a[kk][3] = *reinterpret_cast<const uint32_t*>(&hb[(m0 + g + 8) * HB_S + k0 + 2 * qd + 8]);
        }
#pragma unroll
        for (int kk = 0; kk < 16; ++kk) {
#pragma unroll
            for (int half = 0; half < 2; ++half) {
                int nt = 2 * kk + half;  // fc1 n-tile, n0 = nt*8
                uint4 b01 = *reinterpret_cast<const uint4*>(&g_fc1P[(nt * 64 + lane) * 4]);
                uint4 b23 = *reinterpret_cast<const uint4*>(&g_fc1P[(nt * 64 + 32 + lane) * 4]);
                float c[4] = {0.f, 0.f, 0.f, 0.f};
                mma16816(c, a[0], &b01.x);
                mma16816(c, a[1], &b01.z);
                mma16816(c, a[2], &b23.x);
                mma16816(c, a[3], &b23.z);
                int c0 = nt * 8 + 2 * qd;
                float f0 = __ldg(&fc1b[c0]), f1 = __ldg(&fc1b[c0 + 1]);
                apk[kk][2 * half]     = packbf(fmaxf(c[0] + f0, 0.f), fmaxf(c[1] + f1, 0.f));
                apk[kk][2 * half + 1] = packbf(fmaxf(c[2] + f0, 0.f), fmaxf(c[3] + f1, 0.f));
            }
        }
    }

    // ---- fc2 + residual -> out ----
    {
#pragma unroll
        for (int nt = 0; nt < 8; ++nt) {
            float c[4] = {0.f, 0.f, 0.f, 0.f};
#pragma unroll
            for (int u = 0; u < 8; ++u) {
                uint4 bb = *reinterpret_cast<const uint4*>(&g_fc2P[((nt * 8 + u) * 32 + lane) * 4]);
                mma16816(c, apk[2 * u],     &bb.x);
                mma16816(c, apk[2 * u + 1], &bb.z);
            }
            int c0 = nt * 8 + 2 * qd;
            float f0 = fc2b[c0], f1 = fc2b[c0 + 1];
            float2 x0 = *reinterpret_cast<const float2*>(&xf[(m0 + g)     * XF_S + c0]);
            float2 x1 = *reinterpret_cast<const float2*>(&xf[(m0 + g + 8) * XF_S + c0]);
            float2 o0, o1;
            o0.x = c[0] + f0 + x0.x; o0.y = c[1] + f1 + x0.y;
            o1.x = c[2] + f0 + x1.x; o1.y = c[3] + f1 + x1.y;
            *reinterpret_cast<float2*>(out + ((size_t)s * 64 + m0 + g)     * 64 + c0) = o0;
            *reinterpret_cast<float2*>(out + ((size_t)s * 64 + m0 + g + 8) * 64 + c0) = o1;
        }
    }
}

extern "C" void kernel_launch(void* const* d_in, const int* in_sizes, int n_in,
                              void* d_out, int out_size) {
    (void)in_sizes; (void)n_in; (void)out_size;
    const float* x     = (const float*)d_in[0];
    const float* ln1w  = (const float*)d_in[1];
    const float* ln1b  = (const float*)d_in[2];
    const float* wq    = (const float*)d_in[3];
    const float* wk    = (const float*)d_in[4];
    const float* wv    = (const float*)d_in[5];
    const float* projw = (const float*)d_in[6];
    const float* projb = (const float*)d_in[7];
    const float* ln2w  = (const float*)d_in[8];
    const float* ln2b  = (const float*)d_in[9];
    const float* fc1w  = (const float*)d_in[10];
    const float* fc1b  = (const float*)d_in[11];
    const float* fc2w  = (const float*)d_in[12];
    const float* fc2b  = (const float*)d_in[13];

    cudaFuncSetAttribute(block_kernel, cudaFuncAttributeMaxDynamicSharedMemorySize, SMEM_BYTES);

    prep_kernel<<<32, 256>>>(wq, wk, wv, projw, fc1w, fc2w);
    block_kernel<<<SEQS, 128, SMEM_BYTES>>>(x, ln1w, ln1b, projb, ln2w, ln2b,
                                            fc1b, fc2b, (float*)d_out);
}

// round 5
// speedup vs baseline: 2.4601x; 1.0304x over previous
#include <cuda_runtime.h>
#include <cuda_bf16.h>
#include <stdint.h>

#define SEQS 4096

// Dynamic smem layout (bytes):
//  [0,17408)        float xf[64][68]   residual stream
//  [17408,26624)    bf16  hb[64][72]   LN1 out -> attn out -> LN2 out
//  [26624,44032)    bf16  scr[64][136] q (cols 0..63, pre-scaled), k (cols 64..127)
//  [44032,53248)    bf16  vt[8][8][72] V transposed per head: [head][d][s]
#define SMEM_BYTES 53248
#define XF_S 68
#define HB_S 72
#define SCR_S 136
#define VT_S 72

// q scale: (1/8) * log2(e)  — softmax uses exp2 on pre-scaled scores
#define QSCALE 0.1803368801111204f

// Fragment-packed bf16 weights, coalesced blocks:
//   layout [nt][u][lane][c], c in 0..3 (one uint4 per lane per u-block).
//   kk = 2u + (c>>1), j = c&1; n = nt*8 + (lane>>2); k = kk*16 + 2*(lane&3) + 8*j
//   u32 packs W(k,n), W(k+1,n).
__device__ __align__(16) uint32_t g_wqkvP[24 * 2 * 32 * 4];
__device__ __align__(16) uint32_t g_projP[8 * 2 * 32 * 4];
__device__ __align__(16) uint32_t g_fc1P[32 * 2 * 32 * 4];
__device__ __align__(16) uint32_t g_fc2P[8 * 8 * 32 * 4];

__device__ __forceinline__ uint32_t packbf(float lo, float hi) {
    __nv_bfloat162 t = __floats2bfloat162_rn(lo, hi);
    return *reinterpret_cast<uint32_t*>(&t);
}

__device__ __forceinline__ float ex2(float x) {
    float r;
    asm("ex2.approx.f32 %0, %1;" : "=f"(r) : "f"(x));
    return r;
}

__global__ void prep_kernel(const float* __restrict__ wq, const float* __restrict__ wk,
                            const float* __restrict__ wv, const float* __restrict__ projw,
                            const float* __restrict__ fc1w, const float* __restrict__ fc2w) {
    int stride = gridDim.x * blockDim.x;
    int t0 = blockIdx.x * blockDim.x + threadIdx.x;

    for (int idx = t0; idx < 24 * 2 * 32 * 4; idx += stride) {
        int c = idx & 3, lane = (idx >> 2) & 31, u = (idx >> 7) & 1, nt = idx >> 8;
        int kk = 2 * u + (c >> 1), j = c & 1;
        int n = nt * 8 + (lane >> 2);
        int kb = kk * 16 + 2 * (lane & 3) + 8 * j;
        float v0, v1;
        if (n < 64)       { int h = n >> 3, d = n & 7; v0 = wq[(h * 64 + kb) * 8 + d]; v1 = wq[(h * 64 + kb + 1) * 8 + d]; }
        else if (n < 128) { int m = n - 64;  int h = m >> 3, d = m & 7; v0 = wk[(h * 64 + kb) * 8 + d]; v1 = wk[(h * 64 + kb + 1) * 8 + d]; }
        else              { int m = n - 128; int h = m >> 3, d = m & 7; v0 = wv[(h * 64 + kb) * 8 + d]; v1 = wv[(h * 64 + kb + 1) * 8 + d]; }
        g_wqkvP[idx] = packbf(v0, v1);
    }
    for (int idx = t0; idx < 8 * 2 * 32 * 4; idx += stride) {
        int c = idx & 3, lane = (idx >> 2) & 31, u = (idx >> 7) & 1, nt = idx >> 8;
        int kk = 2 * u + (c >> 1), j = c & 1;
        int n = nt * 8 + (lane >> 2);
        int kb = kk * 16 + 2 * (lane & 3) + 8 * j;
        g_projP[idx] = packbf(projw[kb * 64 + n], projw[(kb + 1) * 64 + n]);
    }
    for (int idx = t0; idx < 32 * 2 * 32 * 4; idx += stride) {
        int c = idx & 3, lane = (idx >> 2) & 31, u = (idx >> 7) & 1, nt = idx >> 8;
        int kk = 2 * u + (c >> 1), j = c & 1;
        int n = nt * 8 + (lane >> 2);
        int kb = kk * 16 + 2 * (lane & 3) + 8 * j;
        g_fc1P[idx] = packbf(fc1w[kb * 256 + n], fc1w[(kb + 1) * 256 + n]);
    }
    for (int idx = t0; idx < 8 * 8 * 32 * 4; idx += stride) {
        int c = idx & 3, lane = (idx >> 2) & 31, u = (idx >> 7) & 7, nt = idx >> 10;
        int kk = 2 * u + (c >> 1), j = c & 1;
        int n = nt * 8 + (lane >> 2);
        int kb = kk * 16 + 2 * (lane & 3) + 8 * j;
        g_fc2P[idx] = packbf(fc2w[kb * 64 + n], fc2w[(kb + 1) * 64 + n]);
    }
}

__device__ __forceinline__ void mma16816(float* c, const uint32_t* a, const uint32_t* b) {
    asm volatile(
        "mma.sync.aligned.m16n8k16.row.col.f32.bf16.bf16.f32 "
        "{%0,%1,%2,%3}, {%4,%5,%6,%7}, {%8,%9}, {%0,%1,%2,%3};\n"
        : "+f"(c[0]), "+f"(c[1]), "+f"(c[2]), "+f"(c[3])
        : "r"(a[0]), "r"(a[1]), "r"(a[2]), "r"(a[3]), "r"(b[0]), "r"(b[1]));
}

__device__ __forceinline__ void mma1688(float* c, const uint32_t* a, uint32_t b) {
    asm volatile(
        "mma.sync.aligned.m16n8k8.row.col.f32.bf16.bf16.f32 "
        "{%0,%1,%2,%3}, {%4,%5}, {%6}, {%0,%1,%2,%3};\n"
        : "+f"(c[0]), "+f"(c[1]), "+f"(c[2]), "+f"(c[3])
        : "r"(a[0]), "r"(a[1]), "r"(b));
}

// LayerNorm: 2 lanes per row. lane -> row m0+(lane>>1), half (lane&1).
__device__ __forceinline__ void ln_fast(const float* xf, __nv_bfloat16* hb,
                                        const float* lnw, const float* lnb,
                                        int m0, int lane) {
    const int r = m0 + (lane >> 1);
    const int h = lane & 1;
    const float* xr = xf + r * XF_S + h * 32;
    float4 xv[8];
#pragma unroll
    for (int i = 0; i < 8; ++i) xv[i] = *reinterpret_cast<const float4*>(xr + 4 * i);
    float sum = 0.f, sq = 0.f;
#pragma unroll
    for (int i = 0; i < 8; ++i) {
        sum += (xv[i].x + xv[i].y) + (xv[i].z + xv[i].w);
        sq = fmaf(xv[i].x, xv[i].x, sq);
        sq = fmaf(xv[i].y, xv[i].y, sq);
        sq = fmaf(xv[i].z, xv[i].z, sq);
        sq = fmaf(xv[i].w, xv[i].w, sq);
    }
    sum += __shfl_xor_sync(0xffffffffu, sum, 1);
    sq  += __shfl_xor_sync(0xffffffffu, sq, 1);
    float mu = sum * 0.015625f;
    float rs = rsqrtf(sq * 0.015625f - mu * mu + 1e-5f);
    __nv_bfloat16* dst = hb + r * HB_S + h * 32;
#pragma unroll
    for (int i = 0; i < 8; ++i) {
        float4 wv = *reinterpret_cast<const float4*>(lnw + h * 32 + 4 * i);
        float4 bv = *reinterpret_cast<const float4*>(lnb + h * 32 + 4 * i);
        uint2 pk;
        pk.x = packbf((xv[i].x - mu) * rs * wv.x + bv.x, (xv[i].y - mu) * rs * wv.y + bv.y);
        pk.y = packbf((xv[i].z - mu) * rs * wv.z + bv.z, (xv[i].w - mu) * rs * wv.w + bv.w);
        *reinterpret_cast<uint2*>(dst + 4 * i) = pk;   // FIXED: 4 bf16 per uint2
    }
}

__global__ __launch_bounds__(128, 4) void block_kernel(
    const float* __restrict__ x,
    const float* __restrict__ ln1w, const float* __restrict__ ln1b,
    const float* __restrict__ projb,
    const float* __restrict__ ln2w, const float* __restrict__ ln2b,
    const float* __restrict__ fc1b, const float* __restrict__ fc2b,
    float* __restrict__ out)
{
    extern __shared__ char smraw[];
    float* xf            = reinterpret_cast<float*>(smraw);                       // [64][68]
    __nv_bfloat16* hb    = reinterpret_cast<__nv_bfloat16*>(smraw + 17408);       // [64][72]
    __nv_bfloat16* scr   = reinterpret_cast<__nv_bfloat16*>(smraw + 26624);       // [64][136]
    __nv_bfloat16* vt    = reinterpret_cast<__nv_bfloat16*>(smraw + 44032);       // [8][8][72]

    const int tid  = threadIdx.x;
    const int w    = tid >> 5;
    const int lane = tid & 31;
    const int g    = lane >> 2;
    const int qd   = lane & 3;
    const int s    = blockIdx.x;
    const int m0   = w * 16;

    // ---- load x tile [64][64] -> xf (stride 68) ----
    {
        const float4* xg = reinterpret_cast<const float4*>(x + (size_t)s * 64 * 64);
        int row = tid >> 1, c0 = (tid & 1) * 32;
#pragma unroll
        for (int i = 0; i < 8; ++i) {
            float4 v = xg[row * 16 + (c0 >> 2) + i];
            *reinterpret_cast<float4*>(&xf[row * XF_S + c0 + 4 * i]) = v;
        }
    }
    __syncthreads();

    // ---- LN1 -> hb ----
    ln_fast(xf, hb, ln1w, ln1b, m0, lane);
    __syncwarp();

    // ---- QKV GEMM: rows m0..m0+15, 192 cols. q (pre-scaled) and k -> scr; v -> vt ----
    {
        uint32_t a[4][4];
#pragma unroll
        for (int kk = 0; kk < 4; ++kk) {
            int k0 = kk * 16;
            a[kk][0] = *reinterpret_cast<const uint32_t*>(&hb[(m0 + g)     * HB_S + k0 + 2 * qd]);
            a[kk][1] = *reinterpret_cast<const uint32_t*>(&hb[(m0 + g + 8) * HB_S + k0 + 2 * qd]);
            a[kk][2] = *reinterpret_cast<const uint32_t*>(&hb[(m0 + g)     * HB_S + k0 + 2 * qd + 8]);
            a[kk][3] = *reinterpret_cast<const uint32_t*>(&hb[(m0 + g + 8) * HB_S + k0 + 2 * qd + 8]);
        }
#pragma unroll 4
        for (int nt = 0; nt < 24; ++nt) {
            uint4 b01 = *reinterpret_cast<const uint4*>(&g_wqkvP[(nt * 64 + lane) * 4]);
            uint4 b23 = *reinterpret_cast<const uint4*>(&g_wqkvP[(nt * 64 + 32 + lane) * 4]);
            float c[4] = {0.f, 0.f, 0.f, 0.f};
            mma16816(c, a[0], &b01.x);
            mma16816(c, a[1], &b01.z);
            mma16816(c, a[2], &b23.x);
            mma16816(c, a[3], &b23.z);
            if (nt < 8) {
                int n0 = nt * 8;
                *reinterpret_cast<uint32_t*>(&scr[(m0 + g)     * SCR_S + n0 + 2 * qd]) =
                    packbf(c[0] * QSCALE, c[1] * QSCALE);
                *reinterpret_cast<uint32_t*>(&scr[(m0 + g + 8) * SCR_S + n0 + 2 * qd]) =
                    packbf(c[2] * QSCALE, c[3] * QSCALE);
            } else if (nt < 16) {
                int n0 = nt * 8;
                *reinterpret_cast<uint32_t*>(&scr[(m0 + g)     * SCR_S + n0 + 2 * qd]) = packbf(c[0], c[1]);
                *reinterpret_cast<uint32_t*>(&scr[(m0 + g + 8) * SCR_S + n0 + 2 * qd]) = packbf(c[2], c[3]);
            } else {
                int head = nt - 16;
                __nv_bfloat16* vh = vt + head * 8 * VT_S;
                vh[(2 * qd)     * VT_S + m0 + g]     = __float2bfloat16(c[0]);
                vh[(2 * qd + 1) * VT_S + m0 + g]     = __float2bfloat16(c[1]);
                vh[(2 * qd)     * VT_S + m0 + g + 8] = __float2bfloat16(c[2]);
                vh[(2 * qd + 1) * VT_S + m0 + g + 8] = __float2bfloat16(c[3]);
            }
        }
    }
    __syncthreads();

    // ---- attention: warp handles heads 2w, 2w+1 over all 64 rows; out -> hb ----
#pragma unroll
    for (int hh = 0; hh < 2; ++hh) {
        const int hd = w * 2 + hh;
        const int qcol = hd * 8, kcol = 64 + hd * 8;
        const __nv_bfloat16* vh = vt + hd * 8 * VT_S;
#pragma unroll
        for (int mt = 0; mt < 4; ++mt) {
            const int t0 = mt * 16;
            const int ntm = 2 * mt + 1;
            uint32_t aq[2];
            aq[0] = *reinterpret_cast<const uint32_t*>(&scr[(t0 + g)     * SCR_S + qcol + 2 * qd]);
            aq[1] = *reinterpret_cast<const uint32_t*>(&scr[(t0 + g + 8) * SCR_S + qcol + 2 * qd]);
            float sc[8][4];
#pragma unroll
            for (int nt = 0; nt < 8; ++nt) {
                if (nt > ntm) continue;
                sc[nt][0] = sc[nt][1] = sc[nt][2] = sc[nt][3] = 0.f;
                uint32_t bk = *reinterpret_cast<const uint32_t*>(&scr[(nt * 8 + g) * SCR_S + kcol + 2 * qd]);
                mma1688(sc[nt], aq, bk);
            }
            const int rlo = t0 + g, rhi = t0 + g + 8;
            // fused mask + exp2 + sum (scores pre-scaled by 0.125*log2e via q)
            float slo = 0.f, shi = 0.f;
#pragma unroll
            for (int nt = 0; nt < 8; ++nt) {
                if (nt > ntm) continue;
#pragma unroll
                for (int e = 0; e < 2; ++e) {
                    int col = nt * 8 + 2 * qd + e;
                    float p0 = (col <= rlo) ? ex2(sc[nt][e])     : 0.f;
                    float p1 = (col <= rhi) ? ex2(sc[nt][2 + e]) : 0.f;
                    sc[nt][e] = p0; sc[nt][2 + e] = p1;
                    slo += p0; shi += p1;
                }
            }
            slo += __shfl_xor_sync(0xffffffffu, slo, 1);
            slo += __shfl_xor_sync(0xffffffffu, slo, 2);
            shi += __shfl_xor_sync(0xffffffffu, shi, 1);
            shi += __shfl_xor_sync(0xffffffffu, shi, 2);
            float acc[4] = {0.f, 0.f, 0.f, 0.f};
#pragma unroll
            for (int kc = 0; kc < 4; ++kc) {
                if (kc > mt) continue;
                uint32_t pa[4];
                pa[0] = packbf(sc[2 * kc][0],     sc[2 * kc][1]);
                pa[1] = packbf(sc[2 * kc][2],     sc[2 * kc][3]);
                pa[2] = packbf(sc[2 * kc + 1][0], sc[2 * kc + 1][1]);
                pa[3] = packbf(sc[2 * kc + 1][2], sc[2 * kc + 1][3]);
                const int sb = kc * 16;
                uint32_t b[2];
                b[0] = *reinterpret_cast<const uint32_t*>(&vh[g * VT_S + sb + 2 * qd]);
                b[1] = *reinterpret_cast<const uint32_t*>(&vh[g * VT_S + sb + 2 * qd + 8]);
                mma16816(acc, pa, b);
            }
            float ilo = 1.f / slo, ihi = 1.f / shi;
            *reinterpret_cast<uint32_t*>(&hb[(t0 + g)     * HB_S + qcol + 2 * qd]) = packbf(acc[0] * ilo, acc[1] * ilo);
            *reinterpret_cast<uint32_t*>(&hb[(t0 + g + 8) * HB_S + qcol + 2 * qd]) = packbf(acc[2] * ihi, acc[3] * ihi);
        }
    }
    __syncthreads();

    // ---- proj + residual into xf ----
    {
        uint32_t a[4][4];
#pragma unroll
        for (int kk = 0; kk < 4; ++kk) {
            int k0 = kk * 16;
            a[kk][0] = *reinterpret_cast<const uint32_t*>(&hb[(m0 + g)     * HB_S + k0 + 2 * qd]);
            a[kk][1] = *reinterpret_cast<const uint32_t*>(&hb[(m0 + g + 8) * HB_S + k0 + 2 * qd]);
            a[kk][2] = *reinterpret_cast<const uint32_t*>(&hb[(m0 + g)     * HB_S + k0 + 2 * qd + 8]);
            a[kk][3] = *reinterpret_cast<const uint32_t*>(&hb[(m0 + g + 8) * HB_S + k0 + 2 * qd + 8]);
        }
#pragma unroll
        for (int nt = 0; nt < 8; ++nt) {
            uint4 b01 = *reinterpret_cast<const uint4*>(&g_projP[(nt * 64 + lane) * 4]);
            uint4 b23 = *reinterpret_cast<const uint4*>(&g_projP[(nt * 64 + 32 + lane) * 4]);
            float c[4] = {0.f, 0.f, 0.f, 0.f};
            mma16816(c, a[0], &b01.x);
            mma16816(c, a[1], &b01.z);
            mma16816(c, a[2], &b23.x);
            mma16816(c, a[3], &b23.z);
            int c0 = nt * 8 + 2 * qd;
            float pb0 = projb[c0], pb1 = projb[c0 + 1];
            float2* p0 = reinterpret_cast<float2*>(&xf[(m0 + g)     * XF_S + c0]);
            float2* p1 = reinterpret_cast<float2*>(&xf[(m0 + g + 8) * XF_S + c0]);
            float2 v0 = *p0, v1 = *p1;
            v0.x += c[0] + pb0; v0.y += c[1] + pb1;
            v1.x += c[2] + pb0; v1.y += c[3] + pb1;
            *p0 = v0; *p1 = v1;
        }
    }
    __syncwarp();

    // ---- LN2 -> hb ----
    ln_fast(xf, hb, ln2w, ln2b, m0, lane);
    __syncwarp();

    // ---- fc1 + relu fused to registers (A-fragments for fc2) ----
    uint32_t apk[16][4];
    {
        uint32_t a[4][4];
#pragma unroll
        for (int kk = 0; kk < 4; ++kk) {
            int k0 = kk * 16;
            a[kk][0] = *reinterpret_cast<const uint32_t*>(&hb[(m0 + g)     * HB_S + k0 + 2 * qd]);
            a[kk][1] = *reinterpret_cast<const uint32_t*>(&hb[(m0 + g + 8) * HB_S + k0 + 2 * qd]);
            a[kk][2] = *reinterpret_cast<const uint32_t*>(&hb[(m0 + g)     * HB_S + k0 + 2 * qd + 8]);
            a[kk][3] = *reinterpret_cast<const uint32_t*>(&hb[(m0 + g + 8) * HB_S + k0 + 2 * qd + 8]);
        }
#pragma unroll
        for (int kk = 0; kk < 16; ++kk) {
#pragma unroll
            for (int half = 0; half < 2; ++half) {
                int nt = 2 * kk + half;
                uint4 b01 = *reinterpret_cast<const uint4*>(&g_fc1P[(nt * 64 + lane) * 4]);
                uint4 b23 = *reinterpret_cast<const uint4*>(&g_fc1P[(nt * 64 + 32 + lane) * 4]);
                float c[4] = {0.f, 0.f, 0.f, 0.f};
                mma16816(c, a[0], &b01.x);
                mma16816(c, a[1], &b01.z);
                mma16816(c, a[2], &b23.x);
                mma16816(c, a[3], &b23.z);
                int c0 = nt * 8 + 2 * qd;
                float f0 = __ldg(&fc1b[c0]), f1 = __ldg(&fc1b[c0 + 1]);
                apk[kk][2 * half]     = packbf(fmaxf(c[0] + f0, 0.f), fmaxf(c[1] + f1, 0.f));
                apk[kk][2 * half + 1] = packbf(fmaxf(c[2] + f0, 0.f), fmaxf(c[3] + f1, 0.f));
            }
        }
    }

    // ---- fc2 + residual -> out ----
    {
#pragma unroll
        for (int nt = 0; nt < 8; ++nt) {
            float c[4] = {0.f, 0.f, 0.f, 0.f};
#pragma unroll
            for (int u = 0; u < 8; ++u) {
                uint4 bb = *reinterpret_cast<const uint4*>(&g_fc2P[((nt * 8 + u) * 32 + lane) * 4]);
                mma16816(c, apk[2 * u],     &bb.x);
                mma16816(c, apk[2 * u + 1], &bb.z);
            }
            int c0 = nt * 8 + 2 * qd;
            float f0 = fc2b[c0], f1 = fc2b[c0 + 1];
            float2 x0 = *reinterpret_cast<const float2*>(&xf[(m0 + g)     * XF_S + c0]);
            float2 x1 = *reinterpret_cast<const float2*>(&xf[(m0 + g + 8) * XF_S + c0]);
            float2 o0, o1;
            o0.x = c[0] + f0 + x0.x; o0.y = c[1] + f1 + x0.y;
            o1.x = c[2] + f0 + x1.x; o1.y = c[3] + f1 + x1.y;
            *reinterpret_cast<float2*>(out + ((size_t)s * 64 + m0 + g)     * 64 + c0) = o0;
            *reinterpret_cast<float2*>(out + ((size_t)s * 64 + m0 + g + 8) * 64 + c0) = o1;
        }
    }
}

extern "C" void kernel_launch(void* const* d_in, const int* in_sizes, int n_in,
                              void* d_out, int out_size) {
    (void)in_sizes; (void)n_in; (void)out_size;
    const float* x     = (const float*)d_in[0];
    const float* ln1w  = (const float*)d_in[1];
    const float* ln1b  = (const float*)d_in[2];
    const float* wq    = (const float*)d_in[3];
    const float* wk    = (const float*)d_in[4];
    const float* wv    = (const float*)d_in[5];
    const float* projw = (const float*)d_in[6];
    const float* projb = (const float*)d_in[7];
    const float* ln2w  = (const float*)d_in[8];
    const float* ln2b  = (const float*)d_in[9];
    const float* fc1w  = (const float*)d_in[10];
    const float* fc1b  = (const float*)d_in[11];
    const float* fc2w  = (const float*)d_in[12];
    const float* fc2b  = (const float*)d_in[13];

    cudaFuncSetAttribute(block_kernel, cudaFuncAttributeMaxDynamicSharedMemorySize, SMEM_BYTES);

    prep_kernel<<<32, 256>>>(wq, wk, wv, projw, fc1w, fc2w);
    block_kernel<<<SEQS, 128, SMEM_BYTES>>>(x, ln1w, ln1b, projb, ln2w, ln2b,
                                            fc1b, fc2b, (float*)d_out);
}